// round 1
// baseline (speedup 1.0000x reference)
#include <cuda_runtime.h>
#include <math.h>
#include <stdint.h>

#define BATCH 32
#define NBOX 24564
#define ROW 93
#define NUM_PRED 10
#define NMS_T 512
#define MAXPT 48   // 512*48 = 24576 >= 24564

typedef unsigned long long u64;

// Scratch (static device globals — no allocation at runtime)
__device__ int    g_count[BATCH];
__device__ float  g_score[BATCH * NBOX];
__device__ int    g_oidx [BATCH * NBOX];
__device__ int    g_cls  [BATCH * NBOX];
__device__ float4 g_box  [BATCH * NBOX];

__global__ void zero_counts_kernel() {
    if (threadIdx.x < BATCH) g_count[threadIdx.x] = 0;
}

// One warp per box. 256 threads = 8 boxes per CTA; grid.y = batch index so a
// CTA never straddles a batch boundary (enables single aggregated atomic).
__global__ __launch_bounds__(256) void decode_kernel(const float* __restrict__ y) {
    const int b    = blockIdx.y;
    const int warp = threadIdx.x >> 5;
    const int lane = threadIdx.x & 31;
    const int box  = blockIdx.x * 8 + warp;

    __shared__ int s_cnt, s_base;
    if (threadIdx.x == 0) s_cnt = 0;
    __syncthreads();

    int slot = -1;
    float sc = 0.0f;
    int cid = 0;
    float4 bx = make_float4(0.f, 0.f, 0.f, 0.f);

    if (box < NBOX) {
        const float* row = y + ((size_t)b * NBOX + box) * ROW;

        // argmax over 81 classes; tie-break = lowest index (matches jnp.argmax)
        float best = row[lane];
        int   bi   = lane;
        float v1 = row[lane + 32];
        if (v1 > best) { best = v1; bi = lane + 32; }
        if (lane < 17) {
            float v2 = row[lane + 64];
            if (v2 > best) { best = v2; bi = lane + 64; }
        }
        #pragma unroll
        for (int o = 16; o > 0; o >>= 1) {
            float ov = __shfl_down_sync(0xffffffffu, best, o);
            int   oi = __shfl_down_sync(0xffffffffu, bi,   o);
            if (ov > best || (ov == best && oi < bi)) { best = ov; bi = oi; }
        }

        if (lane == 0 && bi != 0 && best >= 0.5f) {
            // tail of the row: offsets(4), cxcy(2), wh(2), variances(4)
            float o0 = row[81], o1 = row[82], o2 = row[83], o3 = row[84];
            float cxp = row[85], cyp = row[86], wp = row[87], hp = row[88];
            float va = row[89], vb = row[90], vc = row[91], vd = row[92];

            float cx = o0 * va * wp + cxp;
            float cy = o1 * vb * hp + cyp;
            float w  = (float)exp((double)(o2 * vc)) * wp;  // precise f32-equivalent exp
            float h  = (float)exp((double)(o3 * vd)) * hp;

            bx.x = (cx - 0.5f * w) * 512.0f;
            bx.y = (cy - 0.5f * h) * 512.0f;
            bx.z = (cx + 0.5f * w) * 512.0f;
            bx.w = (cy + 0.5f * h) * 512.0f;
            sc = best;
            cid = bi;
            slot = atomicAdd(&s_cnt, 1);   // shared-mem atomic: cheap
        }
    }
    __syncthreads();
    if (threadIdx.x == 0 && s_cnt > 0) s_base = atomicAdd(&g_count[b], s_cnt);
    __syncthreads();
    if (slot >= 0) {
        int p = b * NBOX + s_base + slot;
        g_score[p] = sc;
        g_oidx[p]  = box;
        g_cls[p]   = cid;
        g_box[p]   = bx;
    }
}

// One CTA per batch item. Candidate "alive" keys held in registers:
// key = (score_bits << 32) | (0xFFFFFFFF - orig_idx)  -> max-reduce reproduces
// "highest score, then lowest original index" exactly. Dead/empty key = 0.
// Greedy NMS: only the first NUM_PRED picks are needed (scores non-increasing,
// so top_k(kept,10) == first 10 picks).
__global__ __launch_bounds__(NMS_T) void nms_kernel(float* __restrict__ out) {
    const int b    = blockIdx.x;
    const int tid  = threadIdx.x;
    const int lane = tid & 31;
    const int wid  = tid >> 5;
    const int base = b * NBOX;
    const int M    = g_count[b];

    __shared__ u64    s_red[16];
    __shared__ int    s_pos;
    __shared__ float4 s_pick;

    // zero the whole output block for this item (d_out is poisoned)
    if (tid < NUM_PRED * 6) out[b * NUM_PRED * 6 + tid] = 0.0f;

    u64 key[MAXPT];
    #pragma unroll
    for (int j = 0; j < MAXPT; j++) {
        int idx = tid + j * NMS_T;
        if (idx < M) {
            float    s = g_score[base + idx];
            unsigned o = (unsigned)g_oidx[base + idx];
            key[j] = ((u64)__float_as_uint(s) << 32) | (u64)(0xFFFFFFFFu - o);
        } else {
            key[j] = 0ull;
        }
    }

    for (int it = 0; it < NUM_PRED; it++) {
        // local max
        u64 best = 0ull;
        #pragma unroll
        for (int j = 0; j < MAXPT; j++) best = key[j] > best ? key[j] : best;
        // warp reduce
        #pragma unroll
        for (int o = 16; o > 0; o >>= 1) {
            u64 v = __shfl_down_sync(0xffffffffu, best, o);
            best = v > best ? v : best;
        }
        __syncthreads();  // protect s_red / s_pick / s_pos reuse across iterations
        if (lane == 0) s_red[wid] = best;
        __syncthreads();
        if (wid == 0) {
            u64 v = s_red[lane & 15];
            #pragma unroll
            for (int o = 8; o > 0; o >>= 1) {
                u64 t = __shfl_down_sync(0xffffffffu, v, o);
                v = t > v ? t : v;
            }
            if (lane == 0) s_red[0] = v;
        }
        __syncthreads();
        u64 bk = s_red[0];
        if (bk == 0ull) break;  // no alive candidates left; rest stays zero

        // owner publishes the compacted position of the winner
        #pragma unroll
        for (int j = 0; j < MAXPT; j++)
            if (key[j] == bk) s_pos = tid + j * NMS_T;
        __syncthreads();

        if (tid == 0) {
            int p = base + s_pos;
            float4 pb = g_box[p];
            s_pick = pb;
            float* o = out + (b * NUM_PRED + it) * 6;
            o[0] = (float)g_cls[p];
            o[1] = __uint_as_float((unsigned)(bk >> 32));
            o[2] = pb.x; o[3] = pb.y; o[4] = pb.z; o[5] = pb.w;
        }
        __syncthreads();

        float4 pk = s_pick;
        float area_q = (pk.z - pk.x) * (pk.w - pk.y);
        #pragma unroll
        for (int j = 0; j < MAXPT; j++) {
            if (key[j] != 0ull) {
                float4 bb = g_box[base + tid + j * NMS_T];
                float iw = fminf(bb.z, pk.z) - fmaxf(bb.x, pk.x); iw = fmaxf(iw, 0.0f);
                float ih = fminf(bb.w, pk.w) - fmaxf(bb.y, pk.y); ih = fmaxf(ih, 0.0f);
                float inter  = iw * ih;
                float area_b = (bb.z - bb.x) * (bb.w - bb.y);
                float iou = inter / (area_b + area_q - inter + 1e-12f);
                if (iou > 0.35f) key[j] = 0ull;  // also suppresses the pick itself (iou=1)
            }
        }
    }
}

extern "C" void kernel_launch(void* const* d_in, const int* in_sizes, int n_in,
                              void* d_out, int out_size) {
    const float* y = (const float*)d_in[0];
    float* out = (float*)d_out;

    zero_counts_kernel<<<1, 32>>>();

    dim3 grid((NBOX + 7) / 8, BATCH);
    decode_kernel<<<grid, 256>>>(y);

    nms_kernel<<<BATCH, NMS_T>>>(out);
}

// round 2
// speedup vs baseline: 2.7449x; 2.7449x over previous
#include <cuda_runtime.h>
#include <math.h>
#include <stdint.h>

#define BATCH 32
#define NBOX 24564
#define ROW 93
#define NUM_PRED 10
#define NMS_T 512
#define NKEY 24576            // 512 * 48, >= NBOX
#define MAXPT 48

typedef unsigned long long u64;

// Scratch (static device globals — zero-initialized at module load)
__device__ int    g_count[BATCH];
__device__ u64    g_key [BATCH * NBOX];
__device__ int    g_cls [BATCH * NBOX];
__device__ float4 g_box [BATCH * NBOX];

// Precise float exp: Cody-Waite range reduction + degree-6 FMA poly (~1 ulp).
// Immune to --use_fast_math (no expf/exp2f/div). Inputs here are ~N(0, 0.1),
// so |x| < 1 in practice; clamp only for paranoia.
__device__ __forceinline__ float exp_precise(float x) {
    x = fminf(fmaxf(x, -80.0f), 80.0f);
    float t  = x * 1.4426950408889634f;
    float kf = rintf(t);
    float r  = fmaf(-kf, 0.6931471824645996f, x);        // ln2 hi
    r        = fmaf(-kf, -1.904654323148236e-09f, r);    // ln2 lo
    float p  = 1.9875691500e-4f;
    p = fmaf(p, r, 1.3981999507e-3f);
    p = fmaf(p, r, 8.3334519073e-3f);
    p = fmaf(p, r, 4.1665795894e-2f);
    p = fmaf(p, r, 1.6666665459e-1f);
    p = fmaf(p, r, 5.0000000000e-1f);
    p = fmaf(p, r, 1.0f);
    p = fmaf(p, r, 1.0f);
    int ki = (int)kf;
    float scale = __int_as_float((ki + 127) << 23);
    return p * scale;
}

// One warp per box; 8 boxes per 256-thread CTA; grid.y = batch index.
__global__ __launch_bounds__(256) void decode_kernel(const float* __restrict__ y) {
    const int b    = blockIdx.y;
    const int warp = threadIdx.x >> 5;
    const int lane = threadIdx.x & 31;
    const int box  = blockIdx.x * 8 + warp;

    __shared__ int s_cnt, s_base;
    if (threadIdx.x == 0) s_cnt = 0;
    __syncthreads();

    int slot = -1;
    u64 key = 0;
    int cid = 0;
    float4 bx = make_float4(0.f, 0.f, 0.f, 0.f);

    if (box < NBOX) {
        const float* row = y + ((size_t)b * NBOX + box) * ROW;

        // argmax over 81 classes; tie-break = lowest index (matches jnp.argmax)
        float best = row[lane];
        int   bi   = lane;
        float v1 = row[lane + 32];
        if (v1 > best) { best = v1; bi = lane + 32; }
        if (lane < 17) {
            float v2 = row[lane + 64];
            if (v2 > best) { best = v2; bi = lane + 64; }
        }
        #pragma unroll
        for (int o = 16; o > 0; o >>= 1) {
            float ov = __shfl_down_sync(0xffffffffu, best, o);
            int   oi = __shfl_down_sync(0xffffffffu, bi,   o);
            if (ov > best || (ov == best && oi < bi)) { best = ov; bi = oi; }
        }

        if (lane == 0 && bi != 0 && best >= 0.5f) {
            float o0 = row[81], o1 = row[82], o2 = row[83], o3 = row[84];
            float cxp = row[85], cyp = row[86], wp = row[87], hp = row[88];
            float va = row[89], vb = row[90], vc = row[91], vd = row[92];

            float cx = o0 * va * wp + cxp;
            float cy = o1 * vb * hp + cyp;
            float w  = exp_precise(o2 * vc) * wp;
            float h  = exp_precise(o3 * vd) * hp;

            bx.x = (cx - 0.5f * w) * 512.0f;
            bx.y = (cy - 0.5f * h) * 512.0f;
            bx.z = (cx + 0.5f * w) * 512.0f;
            bx.w = (cy + 0.5f * h) * 512.0f;
            // key: (score_bits << 32) | (~orig_idx) -> max-reduce == argmax with
            // lowest-original-index tie-break. 0 == dead/empty.
            key = ((u64)__float_as_uint(best) << 32) | (u64)(0xFFFFFFFFu - (unsigned)box);
            cid = bi;
            slot = atomicAdd(&s_cnt, 1);
        }
    }
    __syncthreads();
    if (threadIdx.x == 0 && s_cnt > 0) s_base = atomicAdd(&g_count[b], s_cnt);
    __syncthreads();
    if (slot >= 0) {
        int p = b * NBOX + s_base + slot;
        g_key[p] = key;
        g_cls[p] = cid;
        g_box[p] = bx;
    }
}

// One CTA per image. Keys live in dynamic shared memory (each thread owns a
// strided slice -> no cross-thread key hazards, no register spills).
// Greedy NMS: first NUM_PRED picks == top_k(kept,10) since pick scores are
// non-increasing.
__global__ __launch_bounds__(NMS_T) void nms_kernel(float* __restrict__ out) {
    extern __shared__ u64 s_key[];       // NKEY entries
    const int b    = blockIdx.x;
    const int tid  = threadIdx.x;
    const int lane = tid & 31;
    const int wid  = tid >> 5;
    const int base = b * NBOX;
    const int M    = g_count[b];

    __shared__ u64    s_red[16];
    __shared__ int    s_pos;
    __shared__ float4 s_pick;

    // zero this image's output block (d_out is poisoned)
    if (tid < NUM_PRED * 6) out[b * NUM_PRED * 6 + tid] = 0.0f;

    // load keys; track local max as we go
    u64 best = 0; int bpos = -1;
    #pragma unroll
    for (int j = 0; j < MAXPT; j++) {
        int idx = tid + j * NMS_T;
        u64 k = (idx < M) ? g_key[base + idx] : 0ull;
        s_key[idx] = k;
        if (k > best) { best = k; bpos = idx; }
    }

    for (int it = 0; it < NUM_PRED; it++) {
        // block max-reduce of `best`
        u64 v = best;
        #pragma unroll
        for (int o = 16; o > 0; o >>= 1) {
            u64 t = __shfl_down_sync(0xffffffffu, v, o);
            v = t > v ? t : v;
        }
        __syncthreads();                 // protect s_red/s_pos/s_pick reuse
        if (lane == 0) s_red[wid] = v;
        __syncthreads();
        if (wid == 0) {
            u64 w = s_red[lane & 15];
            #pragma unroll
            for (int o = 8; o > 0; o >>= 1) {
                u64 t = __shfl_down_sync(0xffffffffu, w, o);
                w = t > w ? t : w;
            }
            if (lane == 0) s_red[0] = w;
        }
        __syncthreads();
        u64 bk = s_red[0];
        if (bk == 0ull) break;           // nothing alive; rest stays zero

        if (best == bk) s_pos = bpos;    // keys are unique -> single writer
        __syncthreads();

        if (tid == 0) {
            int p = base + s_pos;
            float4 pb = g_box[p];
            s_pick = pb;
            float* o = out + (b * NUM_PRED + it) * 6;
            o[0] = (float)g_cls[p];
            o[1] = __uint_as_float((unsigned)(bk >> 32));
            o[2] = pb.x; o[3] = pb.y; o[4] = pb.z; o[5] = pb.w;
        }
        __syncthreads();

        // fused suppress + next-iteration local max
        float4 pk = s_pick;
        float area_q = (pk.z - pk.x) * (pk.w - pk.y);
        best = 0; bpos = -1;
        #pragma unroll
        for (int j = 0; j < MAXPT; j++) {
            int idx = tid + j * NMS_T;
            u64 k = s_key[idx];
            if (k != 0ull) {
                float4 bb = g_box[base + idx];
                float iw = fminf(bb.z, pk.z) - fmaxf(bb.x, pk.x); iw = fmaxf(iw, 0.0f);
                float ih = fminf(bb.w, pk.w) - fmaxf(bb.y, pk.y); ih = fmaxf(ih, 0.0f);
                float inter  = iw * ih;
                float area_b = (bb.z - bb.x) * (bb.w - bb.y);
                float iou = inter / (area_b + area_q - inter + 1e-12f);
                if (iou > 0.35f) {
                    s_key[idx] = 0ull;   // also kills the pick itself (iou = 1)
                } else if (k > best) {
                    best = k; bpos = idx;
                }
            }
        }
    }

    // reset this image's counter for the next graph replay
    __syncthreads();
    if (tid == 0) g_count[b] = 0;
}

extern "C" void kernel_launch(void* const* d_in, const int* in_sizes, int n_in,
                              void* d_out, int out_size) {
    const float* y = (const float*)d_in[0];
    float* out = (float*)d_out;

    cudaFuncSetAttribute(nms_kernel, cudaFuncAttributeMaxDynamicSharedMemorySize,
                         NKEY * sizeof(u64));

    dim3 grid((NBOX + 7) / 8, BATCH);
    decode_kernel<<<grid, 256>>>(y);

    nms_kernel<<<BATCH, NMS_T, NKEY * sizeof(u64)>>>(out);
}

// round 3
// speedup vs baseline: 2.9615x; 1.0789x over previous
#include <cuda_runtime.h>
#include <math.h>
#include <stdint.h>

#define BATCH 32
#define NBOX 24564
#define ROW 93
#define NUM_PRED 10
#define NMS_T 512
#define NSCAN 48            // 512 * 48 = 24576 >= NBOX
#define CAP 9472            // smem-resident candidates: 24 B/entry * 9472 = 227,328 B

typedef unsigned long long u64;

// Scratch (static device globals)
__device__ u64    g_key [BATCH * NBOX];   // dense: 0 = dead, else (score|~idx)
__device__ int    g_cls [BATCH * NBOX];   // written only for candidates
__device__ float4 g_box [BATCH * NBOX];   // written only for candidates
__device__ u64    g_ovf_key[BATCH * NBOX];
__device__ float4 g_ovf_box[BATCH * NBOX];

// Precise float exp: Cody-Waite + degree-6 FMA poly (~1 ulp), fast-math-proof.
__device__ __forceinline__ float exp_precise(float x) {
    x = fminf(fmaxf(x, -80.0f), 80.0f);
    float kf = rintf(x * 1.4426950408889634f);
    float r  = fmaf(-kf, 0.6931471824645996f, x);
    r        = fmaf(-kf, -1.904654323148236e-09f, r);
    float p  = 1.9875691500e-4f;
    p = fmaf(p, r, 1.3981999507e-3f);
    p = fmaf(p, r, 8.3334519073e-3f);
    p = fmaf(p, r, 4.1665795894e-2f);
    p = fmaf(p, r, 1.6666665459e-1f);
    p = fmaf(p, r, 5.0000000000e-1f);
    p = fmaf(p, r, 1.0f);
    p = fmaf(p, r, 1.0f);
    float scale = __int_as_float(((int)kf + 127) << 23);
    return p * scale;
}

// One warp per box; 8 boxes per 256-thread CTA; grid.y = batch. No atomics.
__global__ __launch_bounds__(256) void decode_kernel(const float* __restrict__ y) {
    const int b    = blockIdx.y;
    const int warp = threadIdx.x >> 5;
    const int lane = threadIdx.x & 31;
    const int box  = blockIdx.x * 8 + warp;
    if (box >= NBOX) return;

    const float* row = y + ((size_t)b * NBOX + box) * ROW;

    // argmax over 81 classes; tie-break = lowest index (matches jnp.argmax)
    float best = row[lane];
    int   bi   = lane;
    float v1 = row[lane + 32];
    if (v1 > best) { best = v1; bi = lane + 32; }
    if (lane < 17) {
        float v2 = row[lane + 64];
        if (v2 > best) { best = v2; bi = lane + 64; }
    }
    #pragma unroll
    for (int o = 16; o > 0; o >>= 1) {
        float ov = __shfl_down_sync(0xffffffffu, best, o);
        int   oi = __shfl_down_sync(0xffffffffu, bi,   o);
        if (ov > best || (ov == best && oi < bi)) { best = ov; bi = oi; }
    }

    if (lane == 0) {
        const int p = b * NBOX + box;
        if (bi != 0 && best >= 0.5f) {
            float o0 = row[81], o1 = row[82], o2 = row[83], o3 = row[84];
            float cxp = row[85], cyp = row[86], wp = row[87], hp = row[88];
            float va = row[89], vb = row[90], vc = row[91], vd = row[92];

            float cx = o0 * va * wp + cxp;
            float cy = o1 * vb * hp + cyp;
            float w  = exp_precise(o2 * vc) * wp;
            float h  = exp_precise(o3 * vd) * hp;

            float4 bx;
            bx.x = (cx - 0.5f * w) * 512.0f;
            bx.y = (cy - 0.5f * h) * 512.0f;
            bx.z = (cx + 0.5f * w) * 512.0f;
            bx.w = (cy + 0.5f * h) * 512.0f;

            g_key[p] = ((u64)__float_as_uint(best) << 32) |
                       (u64)(0xFFFFFFFFu - (unsigned)box);
            g_cls[p] = bi;
            g_box[p] = bx;
        } else {
            g_key[p] = 0ull;
        }
    }
}

// One CTA per image.
// Phase 1: compact alive keys+boxes into smem (warp-aggregated shared atomic);
//          overflow beyond CAP spills to global (correct for any M).
// Phase 2: greedy NMS, first NUM_PRED picks (== top_k(kept,10) since pick
//          scores are non-increasing). Fused suppress + next-max rescan.
__global__ __launch_bounds__(NMS_T) void nms_kernel(float* __restrict__ out) {
    extern __shared__ __align__(16) char smem_raw[];
    float4* s_box = (float4*)smem_raw;          // CAP
    u64*    s_key = (u64*)(s_box + CAP);        // CAP

    const int b    = blockIdx.x;
    const int tid  = threadIdx.x;
    const int lane = tid & 31;
    const int wid  = tid >> 5;
    const int base = b * NBOX;

    __shared__ int    s_n;
    __shared__ u64    s_red[16];
    __shared__ int    s_pos;
    __shared__ float4 s_pick;

    if (tid == 0) s_n = 0;
    if (tid < NUM_PRED * 6) out[b * NUM_PRED * 6 + tid] = 0.0f;
    __syncthreads();

    // ---- Phase 1: compaction (all threads active every iter for ballot) ----
    #pragma unroll 4
    for (int j = 0; j < NSCAN; j++) {
        int idx = tid + j * NMS_T;
        u64 k = (idx < NBOX) ? g_key[base + idx] : 0ull;
        unsigned mask = __ballot_sync(0xffffffffu, k != 0ull);
        if (k != 0ull) {
            int leader = __ffs(mask) - 1;
            int wbase;
            if (lane == leader) wbase = atomicAdd(&s_n, __popc(mask));
            wbase = __shfl_sync(mask, wbase, leader);
            int slot = wbase + __popc(mask & ((1u << lane) - 1u));
            float4 bb = g_box[base + idx];
            if (slot < CAP) { s_key[slot] = k; s_box[slot] = bb; }
            else            { g_ovf_key[base + slot - CAP] = k;
                              g_ovf_box[base + slot - CAP] = bb; }
        }
    }
    __syncthreads();
    const int M = s_n;
    const int jmax = (M + NMS_T - 1) >> 9;

    // initial local max
    u64 best = 0; int bpos = -1;
    for (int j = 0; j < jmax; j++) {
        int idx = tid + j * NMS_T;
        if (idx < M) {
            u64 k = (idx < CAP) ? s_key[idx] : g_ovf_key[base + idx - CAP];
            if (k > best) { best = k; bpos = idx; }
        }
    }

    // ---- Phase 2: greedy picks ----
    for (int it = 0; it < NUM_PRED; it++) {
        u64 v = best;
        #pragma unroll
        for (int o = 16; o > 0; o >>= 1) {
            u64 t = __shfl_down_sync(0xffffffffu, v, o);
            v = t > v ? t : v;
        }
        __syncthreads();                     // protect s_red/s_pos/s_pick reuse
        if (lane == 0) s_red[wid] = v;
        __syncthreads();
        if (wid == 0) {
            u64 w = s_red[lane & 15];
            #pragma unroll
            for (int o = 8; o > 0; o >>= 1) {
                u64 t = __shfl_down_sync(0xffffffffu, w, o);
                w = t > w ? t : w;
            }
            if (lane == 0) s_red[0] = w;
        }
        __syncthreads();
        u64 bk = s_red[0];
        if (bk == 0ull) break;

        if (best == bk) s_pos = bpos;        // unique keys -> single writer
        __syncthreads();

        if (tid == 0) {
            int sp = s_pos;
            float4 pb = (sp < CAP) ? s_box[sp] : g_ovf_box[base + sp - CAP];
            s_pick = pb;
            unsigned orig = 0xFFFFFFFFu - (unsigned)(bk & 0xFFFFFFFFu);
            float* o = out + (b * NUM_PRED + it) * 6;
            o[0] = (float)g_cls[base + orig];
            o[1] = __uint_as_float((unsigned)(bk >> 32));
            o[2] = pb.x; o[3] = pb.y; o[4] = pb.z; o[5] = pb.w;
        }
        __syncthreads();

        float4 pk = s_pick;
        float area_q = (pk.z - pk.x) * (pk.w - pk.y);
        best = 0; bpos = -1;
        for (int j = 0; j < jmax; j++) {
            int idx = tid + j * NMS_T;
            if (idx < M) {
                bool incap = (idx < CAP);
                u64 k = incap ? s_key[idx] : g_ovf_key[base + idx - CAP];
                if (k != 0ull) {
                    float4 bb = incap ? s_box[idx] : g_ovf_box[base + idx - CAP];
                    float iw = fminf(bb.z, pk.z) - fmaxf(bb.x, pk.x); iw = fmaxf(iw, 0.0f);
                    float ih = fminf(bb.w, pk.w) - fmaxf(bb.y, pk.y); ih = fmaxf(ih, 0.0f);
                    float inter  = iw * ih;
                    float area_b = (bb.z - bb.x) * (bb.w - bb.y);
                    float iou = inter / (area_b + area_q - inter + 1e-12f);
                    if (iou > 0.35f) {
                        if (incap) s_key[idx] = 0ull;
                        else       g_ovf_key[base + idx - CAP] = 0ull;
                    } else if (k > best) {
                        best = k; bpos = idx;
                    }
                }
            }
        }
    }
}

extern "C" void kernel_launch(void* const* d_in, const int* in_sizes, int n_in,
                              void* d_out, int out_size) {
    const float* y = (const float*)d_in[0];
    float* out = (float*)d_out;

    cudaFuncSetAttribute(nms_kernel, cudaFuncAttributeMaxDynamicSharedMemorySize,
                         CAP * 24);

    dim3 grid((NBOX + 7) / 8, BATCH);
    decode_kernel<<<grid, 256>>>(y);

    nms_kernel<<<BATCH, NMS_T, CAP * 24>>>(out);
}

// round 4
// speedup vs baseline: 4.4860x; 1.5148x over previous
#include <cuda_runtime.h>
#include <stdint.h>

#define BATCH 32
#define NBOX 24564
#define ROW 93
#define NUM_PRED 10
#define NMS_T 512
#define NSLOT 24576          // 512*48
#define SLICE 48

typedef unsigned long long u64;

// Scratch (static device globals)
__device__ u64    g_key[BATCH * NBOX];   // dense: 0 = dead, else (score_bits<<32)|(~idx)
__device__ int    g_cls[BATCH * NBOX];   // written only for candidates
__device__ float4 g_box[BATCH * NBOX];   // written only for candidates

// Precise float exp: Cody-Waite + degree-6 FMA poly (~1 ulp), fast-math-proof.
__device__ __forceinline__ float exp_precise(float x) {
    x = fminf(fmaxf(x, -80.0f), 80.0f);
    float kf = rintf(x * 1.4426950408889634f);
    float r  = fmaf(-kf, 0.6931471824645996f, x);
    r        = fmaf(-kf, -1.904654323148236e-09f, r);
    float p  = 1.9875691500e-4f;
    p = fmaf(p, r, 1.3981999507e-3f);
    p = fmaf(p, r, 8.3334519073e-3f);
    p = fmaf(p, r, 4.1665795894e-2f);
    p = fmaf(p, r, 1.6666665459e-1f);
    p = fmaf(p, r, 5.0000000000e-1f);
    p = fmaf(p, r, 1.0f);
    p = fmaf(p, r, 1.0f);
    return p * __int_as_float(((int)kf + 127) << 23);
}

// One warp per box; 8 boxes per 256-thread CTA; grid.y = batch.
// 3 coalesced loads per lane cover the whole 93-float row; tail (cols 81..92)
// extracted via shuffle from the third load — no scalar tail LDGs.
__global__ __launch_bounds__(256) void decode_kernel(const float* __restrict__ y) {
    const int b    = blockIdx.y;
    const int warp = threadIdx.x >> 5;
    const int lane = threadIdx.x & 31;
    const int box  = blockIdx.x * 8 + warp;
    if (box >= NBOX) return;

    const float* row = y + ((size_t)b * NBOX + box) * ROW;

    float c0 = row[lane];
    float c1 = row[lane + 32];
    float c2 = (lane <= 28) ? row[lane + 64] : 0.0f;   // lanes 17..28 carry cols 81..92

    // argmax over 81 classes; tie-break = lowest index (matches jnp.argmax)
    float best = c0; int bi = lane;
    if (c1 > best) { best = c1; bi = lane + 32; }
    if (lane <= 16 && c2 > best) { best = c2; bi = lane + 64; }
    #pragma unroll
    for (int o = 16; o > 0; o >>= 1) {
        float ov = __shfl_down_sync(0xffffffffu, best, o);
        int   oi = __shfl_down_sync(0xffffffffu, bi,   o);
        if (ov > best || (ov == best && oi < bi)) { best = ov; bi = oi; }
    }

    // tail broadcast (cols 81..92 live in c2 of lanes 17..28)
    float o0  = __shfl_sync(0xffffffffu, c2, 17);
    float o1  = __shfl_sync(0xffffffffu, c2, 18);
    float o2  = __shfl_sync(0xffffffffu, c2, 19);
    float o3  = __shfl_sync(0xffffffffu, c2, 20);
    float cxp = __shfl_sync(0xffffffffu, c2, 21);
    float cyp = __shfl_sync(0xffffffffu, c2, 22);
    float wp  = __shfl_sync(0xffffffffu, c2, 23);
    float hp  = __shfl_sync(0xffffffffu, c2, 24);
    float va  = __shfl_sync(0xffffffffu, c2, 25);
    float vb  = __shfl_sync(0xffffffffu, c2, 26);
    float vc  = __shfl_sync(0xffffffffu, c2, 27);
    float vd  = __shfl_sync(0xffffffffu, c2, 28);

    if (lane == 0) {
        const int p = b * NBOX + box;
        if (bi != 0 && best >= 0.5f) {
            float cx = o0 * va * wp + cxp;
            float cy = o1 * vb * hp + cyp;
            float w  = exp_precise(o2 * vc) * wp;
            float h  = exp_precise(o3 * vd) * hp;
            float4 bx;
            bx.x = (cx - 0.5f * w) * 512.0f;
            bx.y = (cy - 0.5f * h) * 512.0f;
            bx.z = (cx + 0.5f * w) * 512.0f;
            bx.w = (cy + 0.5f * h) * 512.0f;
            g_key[p] = ((u64)__float_as_uint(best) << 32) |
                       (u64)(0xFFFFFFFFu - (unsigned)box);
            g_cls[p] = bi;
            g_box[p] = bx;
        } else {
            g_key[p] = 0ull;
        }
    }
}

__device__ __forceinline__ bool iou_gt(const float4& a, const float4& q) {
    float iw = fminf(a.z, q.z) - fmaxf(a.x, q.x); iw = fmaxf(iw, 0.0f);
    float ih = fminf(a.w, q.w) - fmaxf(a.y, q.y); ih = fmaxf(ih, 0.0f);
    float inter  = iw * ih;
    float area_a = (a.z - a.x) * (a.w - a.y);
    float area_q = (q.z - q.x) * (q.w - q.y);
    return inter / (area_a + area_q - inter + 1e-12f) > 0.35f;
}

// One CTA per image. Sorted-order greedy scan:
// each thread exposes a descending head over its 48-key slice (register top-4
// with exact smem refill); heads are kept valid vs current picks; each round,
// block-max of valid heads IS the next pick (exact: per-slice max == head, so
// max of heads == max of all remaining unsuppressed keys).
__global__ __launch_bounds__(NMS_T) void nms_kernel(float* __restrict__ out) {
    extern __shared__ u64 s_raw[];             // NSLOT raw keys (for refills)
    __shared__ u64    s_red[16];
    __shared__ float4 s_pickbox[NUM_PRED];
    __shared__ int    s_np;

    const int b    = blockIdx.x;
    const int tid  = threadIdx.x;
    const int lane = tid & 31;
    const int wid  = tid >> 5;
    const int base = b * NBOX;

    if (tid < NUM_PRED * 6) out[b * NUM_PRED * 6 + tid] = 0.0f;
    if (tid == 0) s_np = 0;

    // load slice + register top-4 (sorted descending; 0 = empty)
    u64 t4a = 0, t4b = 0, t4c = 0, t4d = 0;
    #pragma unroll
    for (int j = 0; j < SLICE; j++) {
        int idx = tid + j * NMS_T;
        u64 k = (idx < NBOX) ? g_key[base + idx] : 0ull;
        s_raw[idx] = k;
        if (k > t4d) {
            if (k > t4a)      { t4d = t4c; t4c = t4b; t4b = t4a; t4a = k; }
            else if (k > t4b) { t4d = t4c; t4c = t4b; t4b = k; }
            else if (k > t4c) { t4d = t4c; t4c = k; }
            else              { t4d = k; }
        }
    }
    __syncthreads();

    int  hpos   = 0;
    u64  head   = t4a;
    float4 hbox = make_float4(0.f, 0.f, 0.f, 0.f);
    bool hload  = false;
    int  hvp    = 0;     // picks already checked against current head

    for (int it = 0; it < NUM_PRED; it++) {
        // ---- validate head vs picks (advance past suppressed entries) ----
        int np = s_np;
        while (head != 0ull) {
            if (!hload) {
                unsigned orig = 0xFFFFFFFFu - (unsigned)head;
                hbox = g_box[base + orig];
                hload = true;
            }
            bool sup = false;
            for (; hvp < np; hvp++)
                if (iou_gt(hbox, s_pickbox[hvp])) { sup = true; break; }
            if (!sup) break;
            // advance head
            hpos++;
            if (hpos == 1)      head = t4b;
            else if (hpos == 2) head = t4c;
            else if (hpos == 3) head = t4d;
            else {
                // exact refill: top-4 of slice keys strictly below t4d
                u64 fl = t4d;
                t4a = t4b = t4c = t4d = 0ull;
                #pragma unroll 8
                for (int j = 0; j < SLICE; j++) {
                    u64 k = s_raw[tid + j * NMS_T];
                    if (k < fl && k > t4d) {
                        if (k > t4a)      { t4d = t4c; t4c = t4b; t4b = t4a; t4a = k; }
                        else if (k > t4b) { t4d = t4c; t4c = t4b; t4b = k; }
                        else if (k > t4c) { t4d = t4c; t4c = k; }
                        else              { t4d = k; }
                    }
                }
                hpos = 0; head = t4a;
            }
            hload = false; hvp = 0;
        }

        // ---- block max of heads ----
        u64 v = head;
        #pragma unroll
        for (int o = 16; o > 0; o >>= 1) {
            u64 t = __shfl_down_sync(0xffffffffu, v, o);
            v = t > v ? t : v;
        }
        __syncthreads();                 // protect s_red reuse
        if (lane == 0) s_red[wid] = v;
        __syncthreads();
        if (wid == 0) {
            u64 w = s_red[lane & 15];
            #pragma unroll
            for (int o = 8; o > 0; o >>= 1) {
                u64 t = __shfl_down_sync(0xffffffffu, w, o);
                w = t > w ? t : w;
            }
            if (lane == 0) s_red[0] = w;
        }
        __syncthreads();
        u64 bk = s_red[0];
        if (bk == 0ull) break;           // nothing left; rest stays zero

        if (head == bk) {                // unique keys -> single owner
            s_pickbox[np] = hbox;
            s_np = np + 1;
            unsigned orig = 0xFFFFFFFFu - (unsigned)bk;
            float* o = out + (b * NUM_PRED + it) * 6;
            o[0] = (float)g_cls[base + orig];
            o[1] = __uint_as_float((unsigned)(bk >> 32));
            o[2] = hbox.x; o[3] = hbox.y; o[4] = hbox.z; o[5] = hbox.w;
            // consume the pick
            hpos++;
            if (hpos == 1)      head = t4b;
            else if (hpos == 2) head = t4c;
            else if (hpos == 3) head = t4d;
            else {
                u64 fl = t4d;
                t4a = t4b = t4c = t4d = 0ull;
                #pragma unroll 8
                for (int j = 0; j < SLICE; j++) {
                    u64 k = s_raw[tid + j * NMS_T];
                    if (k < fl && k > t4d) {
                        if (k > t4a)      { t4d = t4c; t4c = t4b; t4b = t4a; t4a = k; }
                        else if (k > t4b) { t4d = t4c; t4c = t4b; t4b = k; }
                        else if (k > t4c) { t4d = t4c; t4c = k; }
                        else              { t4d = k; }
                    }
                }
                hpos = 0; head = t4a;
            }
            hload = false; hvp = 0;
        }
        __syncthreads();                 // publish new pick before next validate
    }
}

extern "C" void kernel_launch(void* const* d_in, const int* in_sizes, int n_in,
                              void* d_out, int out_size) {
    const float* y = (const float*)d_in[0];
    float* out = (float*)d_out;

    cudaFuncSetAttribute(nms_kernel, cudaFuncAttributeMaxDynamicSharedMemorySize,
                         NSLOT * sizeof(u64));

    dim3 grid((NBOX + 7) / 8, BATCH);
    decode_kernel<<<grid, 256>>>(y);

    nms_kernel<<<BATCH, NMS_T, NSLOT * sizeof(u64)>>>(out);
}

// round 5
// speedup vs baseline: 5.6594x; 1.2615x over previous
#include <cuda_runtime.h>
#include <stdint.h>

#define BATCH 32
#define NBOX 24564
#define ROW 93
#define NUM_PRED 10
#define NMS_T 512
#define SLICE 48            // 512*48 = 24576 >= NBOX
#define DB 128              // boxes per decode CTA

typedef unsigned long long u64;

// Scratch (static device globals)
__device__ u64    g_key[BATCH * NBOX];       // dense: 0 = dead, else (score<<32)|(~idx)
__device__ int    g_cls[BATCH * NBOX];       // written only for candidates
__device__ float4 g_box[BATCH * NBOX];       // written only for candidates
__device__ u64    g_t4 [BATCH * NMS_T * 4];  // per-slice top-4 keys

// Precise float exp: Cody-Waite + degree-6 FMA poly (~1 ulp), fast-math-proof.
__device__ __forceinline__ float exp_precise(float x) {
    x = fminf(fmaxf(x, -80.0f), 80.0f);
    float kf = rintf(x * 1.4426950408889634f);
    float r  = fmaf(-kf, 0.6931471824645996f, x);
    r        = fmaf(-kf, -1.904654323148236e-09f, r);
    float p  = 1.9875691500e-4f;
    p = fmaf(p, r, 1.3981999507e-3f);
    p = fmaf(p, r, 8.3334519073e-3f);
    p = fmaf(p, r, 4.1665795894e-2f);
    p = fmaf(p, r, 1.6666665459e-1f);
    p = fmaf(p, r, 5.0000000000e-1f);
    p = fmaf(p, r, 1.0f);
    p = fmaf(p, r, 1.0f);
    return p * __int_as_float(((int)kf + 127) << 23);
}

// Thread-per-box decode with smem staging: CTA stages 128 contiguous rows via
// coalesced float4 copies, then each thread argmaxes its own row from smem.
// Row stride 93 words -> bank stride 29 (coprime 32) -> conflict-free.
__global__ __launch_bounds__(DB) void decode_kernel(const float* __restrict__ y) {
    __shared__ float s[DB * ROW];            // 47,616 B (fits static 48K)
    const int b  = blockIdx.y;
    const int c0 = blockIdx.x * DB;
    const int nb = min(DB, NBOX - c0);
    const int nf4 = (nb * ROW) >> 2;         // 128*93 and 116*93 both /4 exact

    const float4* src = (const float4*)(y + ((size_t)b * NBOX + c0) * ROW);
    float4* dst = (float4*)s;
    for (int i = threadIdx.x; i < nf4; i += DB) dst[i] = src[i];
    __syncthreads();

    const int t = threadIdx.x;
    if (t >= nb) return;
    const float* row = s + t * ROW;

    // argmax over 81 classes; sequential '>' keeps first occurrence (jnp.argmax)
    float best = row[0]; int bi = 0;
    #pragma unroll
    for (int c = 1; c < 81; c++) {
        float v = row[c];
        if (v > best) { best = v; bi = c; }
    }

    const int box = c0 + t;
    const int p = b * NBOX + box;
    if (bi != 0 && best >= 0.5f) {
        float o0 = row[81], o1 = row[82], o2 = row[83], o3 = row[84];
        float cxp = row[85], cyp = row[86], wp = row[87], hp = row[88];
        float va = row[89], vb = row[90], vc = row[91], vd = row[92];

        float cx = o0 * va * wp + cxp;
        float cy = o1 * vb * hp + cyp;
        float w  = exp_precise(o2 * vc) * wp;
        float h  = exp_precise(o3 * vd) * hp;

        float4 bx;
        bx.x = (cx - 0.5f * w) * 512.0f;
        bx.y = (cy - 0.5f * h) * 512.0f;
        bx.z = (cx + 0.5f * w) * 512.0f;
        bx.w = (cy + 0.5f * h) * 512.0f;

        g_key[p] = ((u64)__float_as_uint(best) << 32) |
                   (u64)(0xFFFFFFFFu - (unsigned)box);
        g_cls[p] = bi;
        g_box[p] = bx;
    } else {
        g_key[p] = 0ull;
    }
}

#define T4_INSERT(k, a, b_, c_, d_)                                  \
    if ((k) > (d_)) {                                                \
        if ((k) > (a))      { d_ = c_; c_ = b_; b_ = a; a = (k); }   \
        else if ((k) > (b_)){ d_ = c_; c_ = b_; b_ = (k); }          \
        else if ((k) > (c_)){ d_ = c_; c_ = (k); }                   \
        else                { d_ = (k); }                            \
    }

// Per-slice top-4 precompute. grid = (2, BATCH) x 256 threads: slice = x*256+tid.
__global__ __launch_bounds__(256) void top4_kernel() {
    const int b = blockIdx.y;
    const int s = blockIdx.x * 256 + threadIdx.x;   // 0..511
    const int base = b * NBOX;

    u64 a = 0, bb = 0, cc = 0, dd = 0;
    #pragma unroll
    for (int j = 0; j < SLICE; j++) {
        int idx = s + j * NMS_T;
        u64 k = (idx < NBOX) ? g_key[base + idx] : 0ull;
        T4_INSERT(k, a, bb, cc, dd)
    }
    u64* o = g_t4 + ((size_t)b * NMS_T + s) * 4;
    o[0] = a; o[1] = bb; o[2] = cc; o[3] = dd;
}

__device__ __forceinline__ bool iou_gt(const float4& a, const float4& q) {
    float iw = fminf(a.z, q.z) - fmaxf(a.x, q.x); iw = fmaxf(iw, 0.0f);
    float ih = fminf(a.w, q.w) - fmaxf(a.y, q.y); ih = fmaxf(ih, 0.0f);
    float inter  = iw * ih;
    float area_a = (a.z - a.x) * (a.w - a.y);
    float area_q = (q.z - q.x) * (q.w - q.y);
    return inter / (area_a + area_q - inter + 1e-12f) > 0.35f;
}

// One CTA per image. Each thread exposes a descending head over its slice
// (precomputed top-4; exact global refill if >4 of its keys get consumed).
// Heads are validated against current picks; block-max of valid heads == next
// greedy pick. First NUM_PRED picks == reference top_k(kept, 10).
__global__ __launch_bounds__(NMS_T) void nms_kernel(float* __restrict__ out) {
    __shared__ u64    s_red[16];
    __shared__ float4 s_pickbox[NUM_PRED];
    __shared__ int    s_np;

    const int b    = blockIdx.x;
    const int tid  = threadIdx.x;
    const int lane = tid & 31;
    const int wid  = tid >> 5;
    const int base = b * NBOX;

    if (tid < NUM_PRED * 6) out[b * NUM_PRED * 6 + tid] = 0.0f;
    if (tid == 0) s_np = 0;

    const u64* t4p = g_t4 + ((size_t)b * NMS_T + tid) * 4;
    u64 t4a = t4p[0], t4b = t4p[1], t4c = t4p[2], t4d = t4p[3];
    __syncthreads();

    int  hpos   = 0;
    u64  head   = t4a;
    float4 hbox = make_float4(0.f, 0.f, 0.f, 0.f);
    bool hload  = false;
    int  hvp    = 0;

    for (int it = 0; it < NUM_PRED; it++) {
        // ---- validate head vs picks; advance past suppressed entries ----
        int np = s_np;
        while (head != 0ull) {
            if (!hload) {
                unsigned orig = 0xFFFFFFFFu - (unsigned)head;
                hbox = g_box[base + orig];
                hload = true;
            }
            bool sup = false;
            for (; hvp < np; hvp++)
                if (iou_gt(hbox, s_pickbox[hvp])) { sup = true; break; }
            if (!sup) break;
            hpos++;
            if (hpos == 1)      head = t4b;
            else if (hpos == 2) head = t4c;
            else if (hpos == 3) head = t4d;
            else {
                // exact refill: top-4 of slice keys strictly below t4d (rare)
                u64 fl = t4d;
                t4a = t4b = t4c = t4d = 0ull;
                for (int j = 0; j < SLICE; j++) {
                    int idx = tid + j * NMS_T;
                    u64 k = (idx < NBOX) ? g_key[base + idx] : 0ull;
                    if (k < fl) { T4_INSERT(k, t4a, t4b, t4c, t4d) }
                }
                hpos = 0; head = t4a;
            }
            hload = false; hvp = 0;
        }

        // ---- block max of heads ----
        u64 v = head;
        #pragma unroll
        for (int o = 16; o > 0; o >>= 1) {
            u64 t = __shfl_down_sync(0xffffffffu, v, o);
            v = t > v ? t : v;
        }
        __syncthreads();
        if (lane == 0) s_red[wid] = v;
        __syncthreads();
        if (wid == 0) {
            u64 w = s_red[lane & 15];
            #pragma unroll
            for (int o = 8; o > 0; o >>= 1) {
                u64 t = __shfl_down_sync(0xffffffffu, w, o);
                w = t > w ? t : w;
            }
            if (lane == 0) s_red[0] = w;
        }
        __syncthreads();
        u64 bk = s_red[0];
        if (bk == 0ull) break;

        if (head == bk) {                    // unique keys -> single owner
            s_pickbox[np] = hbox;
            s_np = np + 1;
            unsigned orig = 0xFFFFFFFFu - (unsigned)bk;
            float* o = out + (b * NUM_PRED + it) * 6;
            o[0] = (float)g_cls[base + orig];
            o[1] = __uint_as_float((unsigned)(bk >> 32));
            o[2] = hbox.x; o[3] = hbox.y; o[4] = hbox.z; o[5] = hbox.w;
            // consume the pick
            hpos++;
            if (hpos == 1)      head = t4b;
            else if (hpos == 2) head = t4c;
            else if (hpos == 3) head = t4d;
            else {
                u64 fl = t4d;
                t4a = t4b = t4c = t4d = 0ull;
                for (int j = 0; j < SLICE; j++) {
                    int idx = tid + j * NMS_T;
                    u64 k = (idx < NBOX) ? g_key[base + idx] : 0ull;
                    if (k < fl) { T4_INSERT(k, t4a, t4b, t4c, t4d) }
                }
                hpos = 0; head = t4a;
            }
            hload = false; hvp = 0;
        }
        __syncthreads();                     // publish pick before next validate
    }
}

extern "C" void kernel_launch(void* const* d_in, const int* in_sizes, int n_in,
                              void* d_out, int out_size) {
    const float* y = (const float*)d_in[0];
    float* out = (float*)d_out;

    dim3 dgrid((NBOX + DB - 1) / DB, BATCH);
    decode_kernel<<<dgrid, DB>>>(y);

    dim3 tgrid(2, BATCH);
    top4_kernel<<<tgrid, 256>>>();

    nms_kernel<<<BATCH, NMS_T>>>(out);
}

// round 6
// speedup vs baseline: 5.8489x; 1.0335x over previous
#include <cuda_runtime.h>
#include <stdint.h>

#define BATCH 32
#define NBOX 24564
#define ROW 93
#define NUM_PRED 10
#define NMS_T 512
#define SLICE 48            // 512*48 = 24576 >= NBOX
#define DB 64               // boxes per decode CTA (23.3KB smem -> 9 CTAs/SM)

typedef unsigned long long u64;

// Scratch (static device globals)
__device__ u64    g_key[BATCH * NBOX];   // dense: 0 = dead, else (score<<32)|(~idx)
__device__ int    g_cls[BATCH * NBOX];   // written only for candidates
__device__ float4 g_box[BATCH * NBOX];   // written only for candidates

// Precise float exp: Cody-Waite + degree-6 FMA poly (~1 ulp), fast-math-proof.
__device__ __forceinline__ float exp_precise(float x) {
    x = fminf(fmaxf(x, -80.0f), 80.0f);
    float kf = rintf(x * 1.4426950408889634f);
    float r  = fmaf(-kf, 0.6931471824645996f, x);
    r        = fmaf(-kf, -1.904654323148236e-09f, r);
    float p  = 1.9875691500e-4f;
    p = fmaf(p, r, 1.3981999507e-3f);
    p = fmaf(p, r, 8.3334519073e-3f);
    p = fmaf(p, r, 4.1665795894e-2f);
    p = fmaf(p, r, 1.6666665459e-1f);
    p = fmaf(p, r, 5.0000000000e-1f);
    p = fmaf(p, r, 1.0f);
    p = fmaf(p, r, 1.0f);
    return p * __int_as_float(((int)kf + 127) << 23);
}

// Thread-per-box decode with smem staging (coalesced float4 copy, then
// per-thread argmax from smem; row stride 93 words -> conflict-free banks).
__global__ __launch_bounds__(DB) void decode_kernel(const float* __restrict__ y) {
    __shared__ float s[DB * ROW];            // 23,808 B -> 9 CTAs/SM
    const int b  = blockIdx.y;
    const int c0 = blockIdx.x * DB;
    const int nb = min(DB, NBOX - c0);       // 64 or 52; both *93 divisible by 4
    const int nf4 = (nb * ROW) >> 2;

    const float4* src = (const float4*)(y + ((size_t)b * NBOX + c0) * ROW);
    float4* dst = (float4*)s;
    for (int i = threadIdx.x; i < nf4; i += DB) dst[i] = src[i];
    __syncthreads();

    const int t = threadIdx.x;
    if (t >= nb) return;
    const float* row = s + t * ROW;

    // argmax over 81 classes; sequential '>' keeps first occurrence (jnp.argmax)
    float best = row[0]; int bi = 0;
    #pragma unroll
    for (int c = 1; c < 81; c++) {
        float v = row[c];
        if (v > best) { best = v; bi = c; }
    }

    const int box = c0 + t;
    const int p = b * NBOX + box;
    if (bi != 0 && best >= 0.5f) {
        float o0 = row[81], o1 = row[82], o2 = row[83], o3 = row[84];
        float cxp = row[85], cyp = row[86], wp = row[87], hp = row[88];
        float va = row[89], vb = row[90], vc = row[91], vd = row[92];

        float cx = o0 * va * wp + cxp;
        float cy = o1 * vb * hp + cyp;
        float w  = exp_precise(o2 * vc) * wp;
        float h  = exp_precise(o3 * vd) * hp;

        float4 bx;
        bx.x = (cx - 0.5f * w) * 512.0f;
        bx.y = (cy - 0.5f * h) * 512.0f;
        bx.z = (cx + 0.5f * w) * 512.0f;
        bx.w = (cy + 0.5f * h) * 512.0f;

        g_key[p] = ((u64)__float_as_uint(best) << 32) |
                   (u64)(0xFFFFFFFFu - (unsigned)box);
        g_cls[p] = bi;
        g_box[p] = bx;
    } else {
        g_key[p] = 0ull;
    }
}

#define T4_INSERT(k, a, b_, c_, d_)                                  \
    if ((k) > (d_)) {                                                \
        if ((k) > (a))      { d_ = c_; c_ = b_; b_ = a; a = (k); }   \
        else if ((k) > (b_)){ d_ = c_; c_ = b_; b_ = (k); }          \
        else if ((k) > (c_)){ d_ = c_; c_ = (k); }                   \
        else                { d_ = (k); }                            \
    }

__device__ __forceinline__ bool iou_gt(const float4& a, const float4& q) {
    float iw = fminf(a.z, q.z) - fmaxf(a.x, q.x); iw = fmaxf(iw, 0.0f);
    float ih = fminf(a.w, q.w) - fmaxf(a.y, q.y); ih = fmaxf(ih, 0.0f);
    float inter  = iw * ih;
    float area_a = (a.z - a.x) * (a.w - a.y);
    float area_q = (q.z - q.x) * (q.w - q.y);
    return inter / (area_a + area_q - inter + 1e-12f) > 0.35f;
}

// One CTA per image. Phase A: per-thread top-4 of its 48-key slice (register,
// fully unrolled coalesced scan) + head-box prefetch. Phase B: sorted-order
// greedy scan — heads validated vs picks, block-max of valid heads == next
// pick. Exact: per-slice iterator never skips; refill rescans global (rare).
__global__ __launch_bounds__(NMS_T) void nms_kernel(float* __restrict__ out) {
    __shared__ u64    s_red[16];
    __shared__ float4 s_pickbox[NUM_PRED];
    __shared__ int    s_np;

    const int b    = blockIdx.x;
    const int tid  = threadIdx.x;
    const int lane = tid & 31;
    const int wid  = tid >> 5;
    const int base = b * NBOX;

    if (tid < NUM_PRED * 6) out[b * NUM_PRED * 6 + tid] = 0.0f;
    if (tid == 0) s_np = 0;

    // ---- Phase A: slice top-4 (coalesced, high MLP) ----
    u64 t4a = 0, t4b = 0, t4c = 0, t4d = 0;
    #pragma unroll
    for (int j = 0; j < SLICE; j++) {
        int idx = tid + j * NMS_T;
        u64 k = (idx < NBOX) ? g_key[base + idx] : 0ull;
        T4_INSERT(k, t4a, t4b, t4c, t4d)
    }

    int  hpos   = 0;
    u64  head   = t4a;
    float4 hbox = make_float4(0.f, 0.f, 0.f, 0.f);
    bool hload  = (head != 0ull);
    int  hvp    = 0;
    if (hload) {                         // prefetch before first barrier
        unsigned orig = 0xFFFFFFFFu - (unsigned)head;
        hbox = g_box[base + orig];
    }
    __syncthreads();

    // ---- Phase B: greedy picks ----
    for (int it = 0; it < NUM_PRED; it++) {
        int np = s_np;
        while (head != 0ull) {
            if (!hload) {
                unsigned orig = 0xFFFFFFFFu - (unsigned)head;
                hbox = g_box[base + orig];
                hload = true;
            }
            bool sup = false;
            for (; hvp < np; hvp++)
                if (iou_gt(hbox, s_pickbox[hvp])) { sup = true; break; }
            if (!sup) break;
            hpos++;
            if (hpos == 1)      head = t4b;
            else if (hpos == 2) head = t4c;
            else if (hpos == 3) head = t4d;
            else {
                // exact refill: top-4 of slice keys strictly below t4d (rare)
                u64 fl = t4d;
                t4a = t4b = t4c = t4d = 0ull;
                for (int j = 0; j < SLICE; j++) {
                    int idx = tid + j * NMS_T;
                    u64 k = (idx < NBOX) ? g_key[base + idx] : 0ull;
                    if (k < fl) { T4_INSERT(k, t4a, t4b, t4c, t4d) }
                }
                hpos = 0; head = t4a;
            }
            hload = false; hvp = 0;
        }

        // block max of heads
        u64 v = head;
        #pragma unroll
        for (int o = 16; o > 0; o >>= 1) {
            u64 t = __shfl_down_sync(0xffffffffu, v, o);
            v = t > v ? t : v;
        }
        __syncthreads();
        if (lane == 0) s_red[wid] = v;
        __syncthreads();
        if (wid == 0) {
            u64 w = s_red[lane & 15];
            #pragma unroll
            for (int o = 8; o > 0; o >>= 1) {
                u64 t = __shfl_down_sync(0xffffffffu, w, o);
                w = t > w ? t : w;
            }
            if (lane == 0) s_red[0] = w;
        }
        __syncthreads();
        u64 bk = s_red[0];
        if (bk == 0ull) break;

        if (head == bk) {                // unique keys -> single owner
            s_pickbox[np] = hbox;
            s_np = np + 1;
            unsigned orig = 0xFFFFFFFFu - (unsigned)bk;
            float* o = out + (b * NUM_PRED + it) * 6;
            o[0] = (float)g_cls[base + orig];
            o[1] = __uint_as_float((unsigned)(bk >> 32));
            o[2] = hbox.x; o[3] = hbox.y; o[4] = hbox.z; o[5] = hbox.w;
            // consume the pick
            hpos++;
            if (hpos == 1)      head = t4b;
            else if (hpos == 2) head = t4c;
            else if (hpos == 3) head = t4d;
            else {
                u64 fl = t4d;
                t4a = t4b = t4c = t4d = 0ull;
                for (int j = 0; j < SLICE; j++) {
                    int idx = tid + j * NMS_T;
                    u64 k = (idx < NBOX) ? g_key[base + idx] : 0ull;
                    if (k < fl) { T4_INSERT(k, t4a, t4b, t4c, t4d) }
                }
                hpos = 0; head = t4a;
            }
            hload = false; hvp = 0;
        }
        __syncthreads();                 // publish pick before next validate
    }
}

extern "C" void kernel_launch(void* const* d_in, const int* in_sizes, int n_in,
                              void* d_out, int out_size) {
    const float* y = (const float*)d_in[0];
    float* out = (float*)d_out;

    dim3 dgrid((NBOX + DB - 1) / DB, BATCH);
    decode_kernel<<<dgrid, DB>>>(y);

    nms_kernel<<<BATCH, NMS_T>>>(out);
}